// round 15
// baseline (speedup 1.0000x reference)
#include <cuda_runtime.h>

// KVCacheHeadAttention: B=32, E=4096 -> D=128, MAX_TOKENS=2048.
// Prefix-softmax: out[b,s,:] = sum_{t<=s} e_t*v[b,t,:] / sum_{t<=s} e_t.
// R15: qkv rebuilt with NO W staging: warp = (m, 8 d-rows), lane = b.
// W via uniform LDG.128 (__ldcs, 8 independent loads/step = MLP 8),
// x from a tiny smem tile (1 LDS.128/step). ~78% FMA issue mix, floor-
// bound (~3us fp32 FMA floor) instead of LDS-latency-chained.
// Score/scan/self-clean unchanged from R13/R14.

#define BB 32
#define DD 128
#define D4 32
#define EE 4096
#define MAXT 2048
#define CHUNK 128
#define SUB 32
#define MAXSUB 64
#define QEC 64            // e-chunk per qkv block

__device__ float g_qkv[3][BB][DD];           // q,k,v (atomic-accumulated)
__device__ float g_e[BB][MAXT];              // exp(scores)
__device__ float g_cnum[BB][MAXSUB][DD];     // 32-token numerator partials
__device__ float g_cden[BB][MAXSUB];         // 32-token denominator partials
__device__ int   g_doneb[BB];                // per-b scan-finished counters

__device__ __forceinline__ float4 f4add(float4 a, float4 b) {
    return make_float4(a.x+b.x, a.y+b.y, a.z+b.z, a.w+b.w);
}
__device__ __forceinline__ float4 f4fma(float s, float4 v, float4 a) {
    return make_float4(fmaf(s,v.x,a.x), fmaf(s,v.y,a.y),
                       fmaf(s,v.z,a.z), fmaf(s,v.w,a.w));
}
__device__ __forceinline__ float4 f4scale(float4 v, float s) {
    return make_float4(v.x*s, v.y*s, v.z*s, v.w*s);
}

// ---- K1: QKV GEMM, uniform-LDG W streaming (grid (6,64), 256 thr) -------
// blockIdx.x: m = bx>>1, dhalf = bx&1. blockIdx.y: esp (64-wide e-slice).
// Warp w owns d-rows dhalf*64 + w*8 .. +8; lane = batch b.
// Step (4 e): 1 LDS.128 (x frag) + 8 uniform LDG.128 (W rows, __ldcs)
// + 32 FMA. Partials atomicAdd'ed into zero-by-contract g_qkv.
__global__ __launch_bounds__(256) void qkv_kernel(
    const float* __restrict__ x,  const float* __restrict__ Wq,
    const float* __restrict__ Wk, const float* __restrict__ Wv) {
    __shared__ float xs[32][QEC + 4];
    int m  = blockIdx.x >> 1;
    int dh = blockIdx.x & 1;
    int e0 = blockIdx.y * QEC;
    const float* W = (m == 0) ? Wq : ((m == 1) ? Wk : Wv);
    int tid = threadIdx.x;

    // x tile 32b x 64e = 512 float4, 2 per thread, coalesced
    for (int i = tid; i < 512; i += 256) {
        int b = i >> 4;
        int j = (i & 15) << 2;
        *(float4*)&xs[b][j] = *(const float4*)(x + (size_t)b * EE + e0 + j);
    }
    __syncthreads();

    int w    = tid >> 5;
    int lane = tid & 31;               // lane = batch b
    int d0   = dh * 64 + w * 8;
    const float* wbase = W + (size_t)d0 * EE + e0;

    float acc[8];
    #pragma unroll
    for (int j = 0; j < 8; j++) acc[j] = 0.0f;

    #pragma unroll 2
    for (int e = 0; e < QEC; e += 4) {
        float4 xv = *(float4*)&xs[lane][e];
        #pragma unroll
        for (int j = 0; j < 8; j++) {
            float4 wv = __ldcs((const float4*)(wbase + (size_t)j * EE + e));
            acc[j] += xv.x*wv.x + xv.y*wv.y + xv.z*wv.z + xv.w*wv.w;
        }
    }
    #pragma unroll
    for (int j = 0; j < 8; j++)
        atomicAdd(&g_qkv[m][lane][d0 + j], acc[j]);
}

// -------- K2: score + 32-token chunk partials (grid nchunks x B) ---------
__global__ __launch_bounds__(512) void score_kernel(
    const float* __restrict__ kv, const int* __restrict__ np, int max_k) {
    int b = blockIdx.y, c = blockIdx.x, tid = threadIdx.x;
    __shared__ float qs[DD], kn[DD], es[CHUNK];
    __shared__ float4 vns4[D4];
    __shared__ float4 red[4][4][D4];

    if (tid < 128) {
        qs[tid] = g_qkv[0][b][tid];
        kn[tid] = g_qkv[1][b][tid];
    } else if (tid < 160) {
        vns4[tid - 128] = *((const float4*)&g_qkv[2][b][0] + (tid - 128));
    }
    __syncthreads();

    int npos = np[b];
    int t0   = c * CHUNK;

    {
        int tok = tid >> 2, qq = tid & 3;
        int t   = t0 + tok;
        float sdot = 0.0f;
        int d0 = qq * 32;
        if (t == npos) {
            #pragma unroll
            for (int d = 0; d < 32; d++) sdot += qs[d0 + d] * kn[d0 + d];
        } else {
            const float4* krow = (const float4*)(kv + ((size_t)b * MAXT + t) * DD) + qq * 8;
            #pragma unroll
            for (int d = 0; d < 8; d++) {
                float4 kk = __ldcs(krow + d);
                sdot += qs[d0+4*d]*kk.x + qs[d0+4*d+1]*kk.y
                      + qs[d0+4*d+2]*kk.z + qs[d0+4*d+3]*kk.w;
            }
        }
        sdot += __shfl_xor_sync(0xffffffffu, sdot, 1);
        sdot += __shfl_xor_sync(0xffffffffu, sdot, 2);
        float e = (t < max_k) ? expf(sdot * 0.08838834764831845f) : 0.0f;
        if (qq == 0) {
            es[tok]   = e;
            g_e[b][t] = e;
        }
    }
    __syncthreads();

    if (tid < 128) {
        float de = es[tid];
        #pragma unroll
        for (int o = 16; o; o >>= 1) de += __shfl_xor_sync(0xffffffffu, de, o);
        if ((tid & 31) == 0) g_cden[b][c * 4 + (tid >> 5)] = de;
    }

    int sc = tid >> 7;
    int tq = (tid >> 5) & 3;
    int d4 = tid & 31;
    int tb = t0 + sc * SUB + tq * 8;
    const float4* vbase = (const float4*)(kv + (size_t)BB * MAXT * DD
                                          + ((size_t)b * MAXT + tb) * DD) + d4;
    float4 acc = make_float4(0.f, 0.f, 0.f, 0.f);
    #pragma unroll
    for (int u = 0; u < 8; u++) {
        float4 vv = vbase[(size_t)u * D4];
        if (tb + u == npos) vv = vns4[d4];
        acc = f4fma(es[sc * SUB + tq * 8 + u], vv, acc);
    }
    red[sc][tq][d4] = acc;
    __syncthreads();
    if (tid < 128) {
        int sc2 = tid >> 5, dd = tid & 31;
        float4 s0 = f4add(f4add(red[sc2][0][dd], red[sc2][1][dd]),
                          f4add(red[sc2][2][dd], red[sc2][3][dd]));
        *((float4*)&g_cnum[b][c * 4 + sc2][0] + dd) = s0;
    }
}

// --------- K3: prefix scan + output + self-clean (grid nchunks x B) ------
__global__ __launch_bounds__(512) void scan_kernel(
    const float* __restrict__ kv, const int* __restrict__ np,
    float* __restrict__ out, int max_k) {
    int b = blockIdx.y, c = blockIdx.x, tid = threadIdx.x;
    __shared__ float es[CHUNK], rden[CHUNK];
    __shared__ float4 vns4[D4];
    __shared__ float4 bred[16][D4];
    __shared__ float4 part[16][D4];
    __shared__ float warp_sums[4];
    __shared__ float denbase_s;
    __shared__ int   lastflag;

    int t0 = c * CHUNK;
    int s  = tid >> 5;
    int d4 = tid & 31;
    int tb = t0 + s * 8;

    const float4* vbase = (const float4*)(kv + (size_t)BB * MAXT * DD
                                          + ((size_t)b * MAXT + tb) * DD) + d4;
    float4 vv[8];
    #pragma unroll
    for (int u = 0; u < 8; u++) vv[u] = vbase[(size_t)u * D4];
    int npos = np[b];
    if (tid < CHUNK) es[tid] = g_e[b][t0 + tid];
    if (tid >= 480) vns4[tid - 480] = *((const float4*)&g_qkv[2][b][0] + (tid - 480));

    {
        float4 acc = make_float4(0.f, 0.f, 0.f, 0.f);
        int nrow = 4 * c;
        for (int i = s; i < nrow; i += 16)
            acc = f4add(acc, *((const float4*)&g_cnum[b][i][0] + d4));
        bred[s][d4] = acc;
    }
    if (tid < 32) {
        float db = 0.0f;
        int nrow = 4 * c;
        for (int i = tid; i < nrow; i += 32) db += g_cden[b][i];
        #pragma unroll
        for (int o = 16; o; o >>= 1) db += __shfl_xor_sync(0xffffffffu, db, o);
        if (tid == 0) denbase_s = db;
    }
    __syncthreads();

    #pragma unroll
    for (int off = 8; off; off >>= 1) {
        if (s < off) bred[s][d4] = f4add(bred[s][d4], bred[s + off][d4]);
        __syncthreads();
    }

    float dv = 0.0f;
    if (tid < 128) {
        dv = es[tid];
        int lane = tid & 31;
        #pragma unroll
        for (int o = 1; o < 32; o <<= 1) {
            float n = __shfl_up_sync(0xffffffffu, dv, o);
            if (lane >= o) dv += n;
        }
        if (lane == 31) warp_sums[tid >> 5] = dv;
    }
    __syncthreads();
    if (tid < 128) {
        int w = tid >> 5;
        float wb = denbase_s;
        for (int i = 0; i < w; i++) wb += warp_sums[i];
        rden[tid] = 1.0f / (wb + dv);
    }

    float4 vn = vns4[d4];
    float4 psum = make_float4(0.f, 0.f, 0.f, 0.f);
    #pragma unroll
    for (int u = 0; u < 8; u++) {
        if (tb + u == npos) vv[u] = vn;
        psum = f4fma(es[s * 8 + u], vv[u], psum);
    }
    part[s][d4] = psum;
    __syncthreads();

    float4 acc = bred[0][d4];
    for (int j = 0; j < s; j++) acc = f4add(acc, part[j][d4]);

    float4* obase = (float4*)(out + ((size_t)b * max_k + tb) * DD) + d4;
    #pragma unroll
    for (int u = 0; u < 8; u++) {
        acc = f4fma(es[s * 8 + u], vv[u], acc);
        if (tb + u < max_k)
            __stcs(obase + (size_t)u * D4, f4scale(acc, rden[s * 8 + u]));
    }

    __syncthreads();
    if (tid == 0)
        lastflag = (atomicAdd(&g_doneb[b], 1) == (int)gridDim.x - 1);
    __syncthreads();
    if (lastflag) {
        if (tid < 3 * DD) g_qkv[tid >> 7][b][tid & 127] = 0.0f;
        if (tid == 0)     g_doneb[b] = 0;
    }
}

// ----------------------------------------------------------------- launch
extern "C" void kernel_launch(void* const* d_in, const int* in_sizes, int n_in,
                              void* d_out, int out_size) {
    const float* x   = (const float*)d_in[0];
    const float* Wq  = (const float*)d_in[1];
    const float* Wk  = (const float*)d_in[2];
    const float* Wv  = (const float*)d_in[3];
    const float* kvc = (const float*)d_in[4];
    const int*   np  = (const int*)d_in[5];
    float* out = (float*)d_out;

    int max_k   = out_size / (BB * DD);
    int nchunks = (max_k + CHUNK - 1) / CHUNK;   // 12 for max_k=1536

    qkv_kernel<<<dim3(6, 64), 256>>>(x, Wq, Wk, Wv);
    score_kernel<<<dim3(nchunks, BB), 512>>>(kvc, np, max_k);
    scan_kernel<<<dim3(nchunks, BB), 512>>>(kvc, np, out, max_k);
}

// round 16
// speedup vs baseline: 1.2645x; 1.2645x over previous
#include <cuda_runtime.h>
#include <cstdint>

// KVCacheHeadAttention: B=32, E=4096 -> D=128, MAX_TOKENS=2048.
// Prefix-softmax: out[b,s,:] = sum_{t<=s} e_t*v[b,t,:] / sum_{t<=s} e_t.
// R16: scan output via TMA bulk store. STG.128 issue cost (12 cyc) caps the
// per-thread store path at ~1.5 TB/s chip-wide == the measured scan ceiling.
// Stage results in smem (STS.128, ~4 cyc) and cp.async.bulk the contiguous
// 64KB chunk to global (TMA path, ~4x throughput). qkv reverted to R13's
// best-measured variant. Score + self-clean unchanged.

#define BB 32
#define DD 128
#define D4 32
#define EE 4096
#define MAXT 2048
#define CHUNK 128
#define SUB 32
#define MAXSUB 64
#define ECH 128

__device__ float g_qkv[3][BB][DD];           // q,k,v (atomic-accumulated)
__device__ float g_e[BB][MAXT];              // exp(scores)
__device__ float g_cnum[BB][MAXSUB][DD];     // 32-token numerator partials
__device__ float g_cden[BB][MAXSUB];         // 32-token denominator partials
__device__ int   g_doneb[BB];                // per-b scan-finished counters

__device__ __forceinline__ float4 f4add(float4 a, float4 b) {
    return make_float4(a.x+b.x, a.y+b.y, a.z+b.z, a.w+b.w);
}
__device__ __forceinline__ float4 f4fma(float s, float4 v, float4 a) {
    return make_float4(fmaf(s,v.x,a.x), fmaf(s,v.y,a.y),
                       fmaf(s,v.z,a.z), fmaf(s,v.w,a.w));
}
__device__ __forceinline__ float4 f4scale(float4 v, float s) {
    return make_float4(v.x*s, v.y*s, v.z*s, v.w*s);
}
__device__ __forceinline__ uint32_t smem_u32(const void* p) {
    uint32_t a;
    asm("{ .reg .u64 t; cvta.to.shared.u64 t, %1; cvt.u32.u64 %0, t; }"
        : "=r"(a) : "l"(p));
    return a;
}

// -------- K1: QKV GEMM, atomic accumulate (grid (12,32), 256 thr) --------
__global__ __launch_bounds__(256) void qkv_kernel(
    const float* __restrict__ x,  const float* __restrict__ Wq,
    const float* __restrict__ Wk, const float* __restrict__ Wv) {
    __shared__ float xs[32][ECH + 4];
    __shared__ float ws[32][ECH + 4];
    int m   = blockIdx.x >> 2;
    int dt  = blockIdx.x & 3;
    int e0  = blockIdx.y * ECH;
    const float* W = (m == 0) ? Wq : ((m == 1) ? Wk : Wv);
    int tid = threadIdx.x;

    for (int i = tid; i < 32 * (ECH / 4); i += 256) {
        int r = i >> 5;
        int j = (i & 31) << 2;
        *(float4*)&xs[r][j] = *(const float4*)(x + (size_t)r * EE + e0 + j);
        *(float4*)&ws[r][j] = __ldcs((const float4*)(W + (size_t)(dt * 32 + r) * EE + e0 + j));
    }
    __syncthreads();

    int ti = tid & 15, tj = tid >> 4;
    float a00 = 0.f, a01 = 0.f, a10 = 0.f, a11 = 0.f;
    #pragma unroll
    for (int e = 0; e < ECH; e += 4) {
        float4 xa = *(float4*)&xs[ti][e];
        float4 xb = *(float4*)&xs[ti + 16][e];
        float4 wa = *(float4*)&ws[tj][e];
        float4 wb = *(float4*)&ws[tj + 16][e];
        a00 += xa.x*wa.x + xa.y*wa.y + xa.z*wa.z + xa.w*wa.w;
        a01 += xa.x*wb.x + xa.y*wb.y + xa.z*wb.z + xa.w*wb.w;
        a10 += xb.x*wa.x + xb.y*wa.y + xb.z*wa.z + xb.w*wa.w;
        a11 += xb.x*wb.x + xb.y*wb.y + xb.z*wb.z + xb.w*wb.w;
    }
    atomicAdd(&g_qkv[m][ti][dt * 32 + tj],           a00);
    atomicAdd(&g_qkv[m][ti][dt * 32 + tj + 16],      a01);
    atomicAdd(&g_qkv[m][ti + 16][dt * 32 + tj],      a10);
    atomicAdd(&g_qkv[m][ti + 16][dt * 32 + tj + 16], a11);
}

// -------- K2: score + 32-token chunk partials (grid nchunks x B) ---------
__global__ __launch_bounds__(512) void score_kernel(
    const float* __restrict__ kv, const int* __restrict__ np, int max_k) {
    int b = blockIdx.y, c = blockIdx.x, tid = threadIdx.x;
    __shared__ float qs[DD], kn[DD], es[CHUNK];
    __shared__ float4 vns4[D4];
    __shared__ float4 red[4][4][D4];

    if (tid < 128) {
        qs[tid] = g_qkv[0][b][tid];
        kn[tid] = g_qkv[1][b][tid];
    } else if (tid < 160) {
        vns4[tid - 128] = *((const float4*)&g_qkv[2][b][0] + (tid - 128));
    }
    __syncthreads();

    int npos = np[b];
    int t0   = c * CHUNK;

    {
        int tok = tid >> 2, qq = tid & 3;
        int t   = t0 + tok;
        float sdot = 0.0f;
        int d0 = qq * 32;
        if (t == npos) {
            #pragma unroll
            for (int d = 0; d < 32; d++) sdot += qs[d0 + d] * kn[d0 + d];
        } else {
            const float4* krow = (const float4*)(kv + ((size_t)b * MAXT + t) * DD) + qq * 8;
            #pragma unroll
            for (int d = 0; d < 8; d++) {
                float4 kk = __ldcs(krow + d);
                sdot += qs[d0+4*d]*kk.x + qs[d0+4*d+1]*kk.y
                      + qs[d0+4*d+2]*kk.z + qs[d0+4*d+3]*kk.w;
            }
        }
        sdot += __shfl_xor_sync(0xffffffffu, sdot, 1);
        sdot += __shfl_xor_sync(0xffffffffu, sdot, 2);
        float e = (t < max_k) ? expf(sdot * 0.08838834764831845f) : 0.0f;
        if (qq == 0) {
            es[tok]   = e;
            g_e[b][t] = e;
        }
    }
    __syncthreads();

    if (tid < 128) {
        float de = es[tid];
        #pragma unroll
        for (int o = 16; o; o >>= 1) de += __shfl_xor_sync(0xffffffffu, de, o);
        if ((tid & 31) == 0) g_cden[b][c * 4 + (tid >> 5)] = de;
    }

    int sc = tid >> 7;
    int tq = (tid >> 5) & 3;
    int d4 = tid & 31;
    int tb = t0 + sc * SUB + tq * 8;
    const float4* vbase = (const float4*)(kv + (size_t)BB * MAXT * DD
                                          + ((size_t)b * MAXT + tb) * DD) + d4;
    float4 acc = make_float4(0.f, 0.f, 0.f, 0.f);
    #pragma unroll
    for (int u = 0; u < 8; u++) {
        float4 vv = vbase[(size_t)u * D4];
        if (tb + u == npos) vv = vns4[d4];
        acc = f4fma(es[sc * SUB + tq * 8 + u], vv, acc);
    }
    red[sc][tq][d4] = acc;
    __syncthreads();
    if (tid < 128) {
        int sc2 = tid >> 5, dd = tid & 31;
        float4 s0 = f4add(f4add(red[sc2][0][dd], red[sc2][1][dd]),
                          f4add(red[sc2][2][dd], red[sc2][3][dd]));
        *((float4*)&g_cnum[b][c * 4 + sc2][0] + dd) = s0;
    }
}

// --------- K3: prefix scan + TMA bulk-store output (grid nchunks x B) ----
__global__ __launch_bounds__(512) void scan_kernel(
    const float* __restrict__ kv, const int* __restrict__ np,
    float* __restrict__ out, int max_k) {
    extern __shared__ float4 sOut[];           // 128 tokens x 32 float4 = 64KB
    __shared__ float es[CHUNK], rden[CHUNK];
    __shared__ float4 vns4[D4];
    __shared__ float4 bred[16][D4];
    __shared__ float4 part[16][D4];
    __shared__ float warp_sums[4];
    __shared__ float denbase_s;
    __shared__ int   lastflag;

    int b = blockIdx.y, c = blockIdx.x, tid = threadIdx.x;
    int t0 = c * CHUNK;
    int s  = tid >> 5;
    int d4 = tid & 31;
    int tb = t0 + s * 8;

    // ---- front-load all global reads ----
    const float4* vbase = (const float4*)(kv + (size_t)BB * MAXT * DD
                                          + ((size_t)b * MAXT + tb) * DD) + d4;
    float4 vv[8];
    #pragma unroll
    for (int u = 0; u < 8; u++) vv[u] = vbase[(size_t)u * D4];
    int npos = np[b];
    if (tid < CHUNK) es[tid] = g_e[b][t0 + tid];
    if (tid >= 480) vns4[tid - 480] = *((const float4*)&g_qkv[2][b][0] + (tid - 480));

    {
        float4 acc = make_float4(0.f, 0.f, 0.f, 0.f);
        int nrow = 4 * c;
        for (int i = s; i < nrow; i += 16)
            acc = f4add(acc, *((const float4*)&g_cnum[b][i][0] + d4));
        bred[s][d4] = acc;
    }
    if (tid < 32) {
        float db = 0.0f;
        int nrow = 4 * c;
        for (int i = tid; i < nrow; i += 32) db += g_cden[b][i];
        #pragma unroll
        for (int o = 16; o; o >>= 1) db += __shfl_xor_sync(0xffffffffu, db, o);
        if (tid == 0) denbase_s = db;
    }
    __syncthreads();

    #pragma unroll
    for (int off = 8; off; off >>= 1) {
        if (s < off) bred[s][d4] = f4add(bred[s][d4], bred[s + off][d4]);
        __syncthreads();
    }

    float dv = 0.0f;
    if (tid < 128) {
        dv = es[tid];
        int lane = tid & 31;
        #pragma unroll
        for (int o = 1; o < 32; o <<= 1) {
            float n = __shfl_up_sync(0xffffffffu, dv, o);
            if (lane >= o) dv += n;
        }
        if (lane == 31) warp_sums[tid >> 5] = dv;
    }
    __syncthreads();
    if (tid < 128) {
        int w = tid >> 5;
        float wb = denbase_s;
        for (int i = 0; i < w; i++) wb += warp_sums[i];
        rden[tid] = 1.0f / (wb + dv);
    }

    float4 vn = vns4[d4];
    float4 psum = make_float4(0.f, 0.f, 0.f, 0.f);
    #pragma unroll
    for (int u = 0; u < 8; u++) {
        if (tb + u == npos) vv[u] = vn;
        psum = f4fma(es[s * 8 + u], vv[u], psum);
    }
    part[s][d4] = psum;
    __syncthreads();

    float4 acc = bred[0][d4];
    for (int j = 0; j < s; j++) acc = f4add(acc, part[j][d4]);

    // scan -> smem staging (STS.128, conflict-free: lane d4 hits banks 4*d4..)
    #pragma unroll
    for (int u = 0; u < 8; u++) {
        acc = f4fma(es[s * 8 + u], vv[u], acc);
        sOut[(s * 8 + u) * D4 + d4] = f4scale(acc, rden[s * 8 + u]);
    }
    __syncthreads();

    // ---- TMA bulk store: one contiguous copy smem -> out[b, t0:t0+nt, :] --
    asm volatile("fence.proxy.async.shared::cta;" ::: "memory");
    if (tid == 0) {
        int nt = max_k - t0; if (nt > CHUNK) nt = CHUNK;
        float* gdst = out + ((size_t)b * max_k + t0) * DD;
        uint32_t ssrc = smem_u32(sOut);
        uint32_t bytes = (uint32_t)nt * DD * 4;
        asm volatile(
            "cp.async.bulk.global.shared::cta.bulk_group [%0], [%1], %2;"
            :: "l"(gdst), "r"(ssrc), "r"(bytes) : "memory");
        asm volatile("cp.async.bulk.commit_group;" ::: "memory");
        asm volatile("cp.async.bulk.wait_group 0;" ::: "memory");
    }

    // ---- self-clean g_qkv[.][b] for next replay (increment-after-use) ----
    __syncthreads();
    if (tid == 0)
        lastflag = (atomicAdd(&g_doneb[b], 1) == (int)gridDim.x - 1);
    __syncthreads();
    if (lastflag) {
        if (tid < 3 * DD) g_qkv[tid >> 7][b][tid & 127] = 0.0f;
        if (tid == 0)     g_doneb[b] = 0;
    }
}

// ----------------------------------------------------------------- launch
extern "C" void kernel_launch(void* const* d_in, const int* in_sizes, int n_in,
                              void* d_out, int out_size) {
    const float* x   = (const float*)d_in[0];
    const float* Wq  = (const float*)d_in[1];
    const float* Wk  = (const float*)d_in[2];
    const float* Wv  = (const float*)d_in[3];
    const float* kvc = (const float*)d_in[4];
    const int*   np  = (const int*)d_in[5];
    float* out = (float*)d_out;

    int max_k   = out_size / (BB * DD);
    int nchunks = (max_k + CHUNK - 1) / CHUNK;   // 12 for max_k=1536

    static bool attr_set = false;                // idempotent attribute set
    if (!attr_set) {
        cudaFuncSetAttribute(scan_kernel,
                             cudaFuncAttributeMaxDynamicSharedMemorySize,
                             CHUNK * DD * 4);
        attr_set = true;
    }

    qkv_kernel<<<dim3(12, 32), 256>>>(x, Wq, Wk, Wv);
    score_kernel<<<dim3(nchunks, BB), 512>>>(kvc, np, max_k);
    scan_kernel<<<dim3(nchunks, BB), 512, CHUNK * DD * 4>>>(kvc, np, out, max_k);
}

// round 17
// speedup vs baseline: 1.2731x; 1.0068x over previous
#include <cuda_runtime.h>
#include <cstdint>

// KVCacheHeadAttention: B=32, E=4096 -> D=128, MAX_TOKENS=2048.
// Prefix-softmax: out[b,s,:] = sum_{t<=s} e_t*v[b,t,:] / sum_{t<=s} e_t.
// R17 = R16 with ALL __ldcs removed (single-variable experiment).
// Ledger: every qkv >= 11.7us carried __ldcs on the W load; the only
// configs with inferred-faster qkv (R2/R3, ~6-8us) used plain loads.
// .cs (evict-first) likely demotes L1 sector handling for the shared
// W/x tiles. TMA bulk-store scan, self-cleaning state, geometry unchanged.

#define BB 32
#define DD 128
#define D4 32
#define EE 4096
#define MAXT 2048
#define CHUNK 128
#define SUB 32
#define MAXSUB 64
#define ECH 128

__device__ float g_qkv[3][BB][DD];           // q,k,v (atomic-accumulated)
__device__ float g_e[BB][MAXT];              // exp(scores)
__device__ float g_cnum[BB][MAXSUB][DD];     // 32-token numerator partials
__device__ float g_cden[BB][MAXSUB];         // 32-token denominator partials
__device__ int   g_doneb[BB];                // per-b scan-finished counters

__device__ __forceinline__ float4 f4add(float4 a, float4 b) {
    return make_float4(a.x+b.x, a.y+b.y, a.z+b.z, a.w+b.w);
}
__device__ __forceinline__ float4 f4fma(float s, float4 v, float4 a) {
    return make_float4(fmaf(s,v.x,a.x), fmaf(s,v.y,a.y),
                       fmaf(s,v.z,a.z), fmaf(s,v.w,a.w));
}
__device__ __forceinline__ float4 f4scale(float4 v, float s) {
    return make_float4(v.x*s, v.y*s, v.z*s, v.w*s);
}
__device__ __forceinline__ uint32_t smem_u32(const void* p) {
    uint32_t a;
    asm("{ .reg .u64 t; cvta.to.shared.u64 t, %1; cvt.u32.u64 %0, t; }"
        : "=r"(a) : "l"(p));
    return a;
}

// -------- K1: QKV GEMM, atomic accumulate (grid (12,32), 256 thr) --------
__global__ __launch_bounds__(256) void qkv_kernel(
    const float* __restrict__ x,  const float* __restrict__ Wq,
    const float* __restrict__ Wk, const float* __restrict__ Wv) {
    __shared__ float xs[32][ECH + 4];
    __shared__ float ws[32][ECH + 4];
    int m   = blockIdx.x >> 2;
    int dt  = blockIdx.x & 3;
    int e0  = blockIdx.y * ECH;
    const float* W = (m == 0) ? Wq : ((m == 1) ? Wk : Wv);
    int tid = threadIdx.x;

    for (int i = tid; i < 32 * (ECH / 4); i += 256) {
        int r = i >> 5;
        int j = (i & 31) << 2;
        *(float4*)&xs[r][j] = *(const float4*)(x + (size_t)r * EE + e0 + j);
        *(float4*)&ws[r][j] = *(const float4*)(W + (size_t)(dt * 32 + r) * EE + e0 + j);
    }
    __syncthreads();

    int ti = tid & 15, tj = tid >> 4;
    float a00 = 0.f, a01 = 0.f, a10 = 0.f, a11 = 0.f;
    #pragma unroll
    for (int e = 0; e < ECH; e += 4) {
        float4 xa = *(float4*)&xs[ti][e];
        float4 xb = *(float4*)&xs[ti + 16][e];
        float4 wa = *(float4*)&ws[tj][e];
        float4 wb = *(float4*)&ws[tj + 16][e];
        a00 += xa.x*wa.x + xa.y*wa.y + xa.z*wa.z + xa.w*wa.w;
        a01 += xa.x*wb.x + xa.y*wb.y + xa.z*wb.z + xa.w*wb.w;
        a10 += xb.x*wa.x + xb.y*wa.y + xb.z*wa.z + xb.w*wa.w;
        a11 += xb.x*wb.x + xb.y*wb.y + xb.z*wb.z + xb.w*wb.w;
    }
    atomicAdd(&g_qkv[m][ti][dt * 32 + tj],           a00);
    atomicAdd(&g_qkv[m][ti][dt * 32 + tj + 16],      a01);
    atomicAdd(&g_qkv[m][ti + 16][dt * 32 + tj],      a10);
    atomicAdd(&g_qkv[m][ti + 16][dt * 32 + tj + 16], a11);
}

// -------- K2: score + 32-token chunk partials (grid nchunks x B) ---------
__global__ __launch_bounds__(512) void score_kernel(
    const float* __restrict__ kv, const int* __restrict__ np, int max_k) {
    int b = blockIdx.y, c = blockIdx.x, tid = threadIdx.x;
    __shared__ float qs[DD], kn[DD], es[CHUNK];
    __shared__ float4 vns4[D4];
    __shared__ float4 red[4][4][D4];

    if (tid < 128) {
        qs[tid] = g_qkv[0][b][tid];
        kn[tid] = g_qkv[1][b][tid];
    } else if (tid < 160) {
        vns4[tid - 128] = *((const float4*)&g_qkv[2][b][0] + (tid - 128));
    }
    __syncthreads();

    int npos = np[b];
    int t0   = c * CHUNK;

    {
        int tok = tid >> 2, qq = tid & 3;
        int t   = t0 + tok;
        float sdot = 0.0f;
        int d0 = qq * 32;
        if (t == npos) {
            #pragma unroll
            for (int d = 0; d < 32; d++) sdot += qs[d0 + d] * kn[d0 + d];
        } else {
            const float4* krow = (const float4*)(kv + ((size_t)b * MAXT + t) * DD) + qq * 8;
            #pragma unroll
            for (int d = 0; d < 8; d++) {
                float4 kk = krow[d];
                sdot += qs[d0+4*d]*kk.x + qs[d0+4*d+1]*kk.y
                      + qs[d0+4*d+2]*kk.z + qs[d0+4*d+3]*kk.w;
            }
        }
        sdot += __shfl_xor_sync(0xffffffffu, sdot, 1);
        sdot += __shfl_xor_sync(0xffffffffu, sdot, 2);
        float e = (t < max_k) ? expf(sdot * 0.08838834764831845f) : 0.0f;
        if (qq == 0) {
            es[tok]   = e;
            g_e[b][t] = e;
        }
    }
    __syncthreads();

    if (tid < 128) {
        float de = es[tid];
        #pragma unroll
        for (int o = 16; o; o >>= 1) de += __shfl_xor_sync(0xffffffffu, de, o);
        if ((tid & 31) == 0) g_cden[b][c * 4 + (tid >> 5)] = de;
    }

    int sc = tid >> 7;
    int tq = (tid >> 5) & 3;
    int d4 = tid & 31;
    int tb = t0 + sc * SUB + tq * 8;
    const float4* vbase = (const float4*)(kv + (size_t)BB * MAXT * DD
                                          + ((size_t)b * MAXT + tb) * DD) + d4;
    float4 acc = make_float4(0.f, 0.f, 0.f, 0.f);
    #pragma unroll
    for (int u = 0; u < 8; u++) {
        float4 vv = vbase[(size_t)u * D4];
        if (tb + u == npos) vv = vns4[d4];
        acc = f4fma(es[sc * SUB + tq * 8 + u], vv, acc);
    }
    red[sc][tq][d4] = acc;
    __syncthreads();
    if (tid < 128) {
        int sc2 = tid >> 5, dd = tid & 31;
        float4 s0 = f4add(f4add(red[sc2][0][dd], red[sc2][1][dd]),
                          f4add(red[sc2][2][dd], red[sc2][3][dd]));
        *((float4*)&g_cnum[b][c * 4 + sc2][0] + dd) = s0;
    }
}

// --------- K3: prefix scan + TMA bulk-store output (grid nchunks x B) ----
__global__ __launch_bounds__(512) void scan_kernel(
    const float* __restrict__ kv, const int* __restrict__ np,
    float* __restrict__ out, int max_k) {
    extern __shared__ float4 sOut[];           // 128 tokens x 32 float4 = 64KB
    __shared__ float es[CHUNK], rden[CHUNK];
    __shared__ float4 vns4[D4];
    __shared__ float4 bred[16][D4];
    __shared__ float4 part[16][D4];
    __shared__ float warp_sums[4];
    __shared__ float denbase_s;
    __shared__ int   lastflag;

    int b = blockIdx.y, c = blockIdx.x, tid = threadIdx.x;
    int t0 = c * CHUNK;
    int s  = tid >> 5;
    int d4 = tid & 31;
    int tb = t0 + s * 8;

    const float4* vbase = (const float4*)(kv + (size_t)BB * MAXT * DD
                                          + ((size_t)b * MAXT + tb) * DD) + d4;
    float4 vv[8];
    #pragma unroll
    for (int u = 0; u < 8; u++) vv[u] = vbase[(size_t)u * D4];
    int npos = np[b];
    if (tid < CHUNK) es[tid] = g_e[b][t0 + tid];
    if (tid >= 480) vns4[tid - 480] = *((const float4*)&g_qkv[2][b][0] + (tid - 480));

    {
        float4 acc = make_float4(0.f, 0.f, 0.f, 0.f);
        int nrow = 4 * c;
        for (int i = s; i < nrow; i += 16)
            acc = f4add(acc, *((const float4*)&g_cnum[b][i][0] + d4));
        bred[s][d4] = acc;
    }
    if (tid < 32) {
        float db = 0.0f;
        int nrow = 4 * c;
        for (int i = tid; i < nrow; i += 32) db += g_cden[b][i];
        #pragma unroll
        for (int o = 16; o; o >>= 1) db += __shfl_xor_sync(0xffffffffu, db, o);
        if (tid == 0) denbase_s = db;
    }
    __syncthreads();

    #pragma unroll
    for (int off = 8; off; off >>= 1) {
        if (s < off) bred[s][d4] = f4add(bred[s][d4], bred[s + off][d4]);
        __syncthreads();
    }

    float dv = 0.0f;
    if (tid < 128) {
        dv = es[tid];
        int lane = tid & 31;
        #pragma unroll
        for (int o = 1; o < 32; o <<= 1) {
            float n = __shfl_up_sync(0xffffffffu, dv, o);
            if (lane >= o) dv += n;
        }
        if (lane == 31) warp_sums[tid >> 5] = dv;
    }
    __syncthreads();
    if (tid < 128) {
        int w = tid >> 5;
        float wb = denbase_s;
        for (int i = 0; i < w; i++) wb += warp_sums[i];
        rden[tid] = 1.0f / (wb + dv);
    }

    float4 vn = vns4[d4];
    float4 psum = make_float4(0.f, 0.f, 0.f, 0.f);
    #pragma unroll
    for (int u = 0; u < 8; u++) {
        if (tb + u == npos) vv[u] = vn;
        psum = f4fma(es[s * 8 + u], vv[u], psum);
    }
    part[s][d4] = psum;
    __syncthreads();

    float4 acc = bred[0][d4];
    for (int j = 0; j < s; j++) acc = f4add(acc, part[j][d4]);

    // scan -> smem staging (STS.128)
    #pragma unroll
    for (int u = 0; u < 8; u++) {
        acc = f4fma(es[s * 8 + u], vv[u], acc);
        sOut[(s * 8 + u) * D4 + d4] = f4scale(acc, rden[s * 8 + u]);
    }
    __syncthreads();

    // TMA bulk store: one contiguous copy smem -> out[b, t0:t0+nt, :]
    asm volatile("fence.proxy.async.shared::cta;" ::: "memory");
    if (tid == 0) {
        int nt = max_k - t0; if (nt > CHUNK) nt = CHUNK;
        float* gdst = out + ((size_t)b * max_k + t0) * DD;
        uint32_t ssrc = smem_u32(sOut);
        uint32_t bytes = (uint32_t)nt * DD * 4;
        asm volatile(
            "cp.async.bulk.global.shared::cta.bulk_group [%0], [%1], %2;"
            :: "l"(gdst), "r"(ssrc), "r"(bytes) : "memory");
        asm volatile("cp.async.bulk.commit_group;" ::: "memory");
        asm volatile("cp.async.bulk.wait_group 0;" ::: "memory");
    }

    // self-clean g_qkv[.][b] for next replay (increment-after-use)
    __syncthreads();
    if (tid == 0)
        lastflag = (atomicAdd(&g_doneb[b], 1) == (int)gridDim.x - 1);
    __syncthreads();
    if (lastflag) {
        if (tid < 3 * DD) g_qkv[tid >> 7][b][tid & 127] = 0.0f;
        if (tid == 0)     g_doneb[b] = 0;
    }
}

// ----------------------------------------------------------------- launch
extern "C" void kernel_launch(void* const* d_in, const int* in_sizes, int n_in,
                              void* d_out, int out_size) {
    const float* x   = (const float*)d_in[0];
    const float* Wq  = (const float*)d_in[1];
    const float* Wk  = (const float*)d_in[2];
    const float* Wv  = (const float*)d_in[3];
    const float* kvc = (const float*)d_in[4];
    const int*   np  = (const int*)d_in[5];
    float* out = (float*)d_out;

    int max_k   = out_size / (BB * DD);
    int nchunks = (max_k + CHUNK - 1) / CHUNK;   // 12 for max_k=1536

    static bool attr_set = false;
    if (!attr_set) {
        cudaFuncSetAttribute(scan_kernel,
                             cudaFuncAttributeMaxDynamicSharedMemorySize,
                             CHUNK * DD * 4);
        attr_set = true;
    }

    qkv_kernel<<<dim3(12, 32), 256>>>(x, Wq, Wk, Wv);
    score_kernel<<<dim3(nchunks, BB), 512>>>(kvc, np, max_k);
    scan_kernel<<<dim3(nchunks, BB), 512, CHUNK * DD * 4>>>(kvc, np, out, max_k);
}